// round 12
// baseline (speedup 1.0000x reference)
#include <cuda_runtime.h>
#include <cuda_bf16.h>
#include <cuda_fp16.h>
#include <math.h>
#include <cstdint>

// Problem shape (fixed): B=8192, D=H=1024, 4H=4096
#define BB   8192
#define HH   1024
#define FH   4096
#define KK   1024
#define EPSL 1e-5f

// ---------------------------------------------------------------------------
// Static device scratch
// ---------------------------------------------------------------------------
__device__ __half g_g16[2][(size_t)BB * FH];
__device__ __half g_ah[2][(size_t)BB * KK];
__device__ __half g_wh[2][(size_t)FH * KK];

// ---------------------------------------------------------------------------
// helpers
// ---------------------------------------------------------------------------
__device__ __forceinline__ uint32_t smem_u32(const void* p) {
    uint32_t a;
    asm("{ .reg .u64 t; cvta.to.shared.u64 t, %1; cvt.u32.u64 %0, t; }"
        : "=r"(a) : "l"(p));
    return a;
}

__device__ __forceinline__ void ldmx4(uint32_t* r, uint32_t addr) {
    asm volatile("ldmatrix.sync.aligned.m8n8.x4.shared.b16 {%0,%1,%2,%3}, [%4];"
                 : "=r"(r[0]), "=r"(r[1]), "=r"(r[2]), "=r"(r[3]) : "r"(addr));
}

__device__ __forceinline__ void mma_f16(float* d, const uint32_t* a,
                                        const uint32_t* b) {
    asm volatile(
        "mma.sync.aligned.m16n8k16.row.col.f32.f16.f16.f32 "
        "{%0,%1,%2,%3}, {%4,%5,%6,%7}, {%8,%9}, {%0,%1,%2,%3};"
        : "+f"(d[0]), "+f"(d[1]), "+f"(d[2]), "+f"(d[3])
        : "r"(a[0]), "r"(a[1]), "r"(a[2]), "r"(a[3]), "r"(b[0]), "r"(b[1]));
}

// fast transcendentals (forced MUFU path, overflow-safe for |x| < 80)
__device__ __forceinline__ float fsig(float x) {
    return __fdividef(1.f, 1.f + __expf(-x));
}
__device__ __forceinline__ float ftanh(float x) {
    float ax = fabsf(x);
    float t  = __expf(-2.f * ax);
    float r  = __fdividef(1.f - t, 1.f + t);
    return copysignf(r, x);
}

// ---------------------------------------------------------------------------
// Merged conversion kernel.
// ---------------------------------------------------------------------------
__global__ void __launch_bounds__(256)
conv_all(const float* __restrict__ h0, const float* __restrict__ x,
         const float* __restrict__ Wh, const float* __restrict__ Wx)
{
    const int bid = blockIdx.x;
    if (bid < 16384) {
        const int which = bid >> 13;
        const float* in = which ? x : h0;
        size_t i = (size_t)(bid & 8191) * 256 + threadIdx.x;   // float4 index
        float4 v = reinterpret_cast<const float4*>(in)[i];
        __half2 p0 = __floats2half2_rn(v.x, v.y);
        __half2 p1 = __floats2half2_rn(v.z, v.w);
        __half2* dst = reinterpret_cast<__half2*>(g_ah[which]);
        dst[2 * i + 0] = p0;
        dst[2 * i + 1] = p1;
    } else {
        __shared__ float ts[32][33];
        int r = bid - 16384;
        const int which = r >> 12;
        r &= 4095;
        const float* W = which ? Wx : Wh;
        int n0 = (r & 127) * 32, k0 = (r >> 7) * 32;
        int tx = threadIdx.x & 31, ty = threadIdx.x >> 5;   // ty 0..7
#pragma unroll
        for (int d = 0; d < 32; d += 8)
            ts[ty + d][tx] = W[(size_t)(k0 + ty + d) * FH + n0 + tx];
        __syncthreads();
#pragma unroll
        for (int d = 0; d < 4; d++) {
            int nl = ty + d * 8;
            float v = ts[tx][nl];
            g_wh[which][(size_t)(n0 + nl) * KK + k0 + tx] =
                __float2half_rn(32.0f * v);
        }
    }
}

// ---------------------------------------------------------------------------
// GEMM: G16[M,N] = fp16( (Ah @ (32*W)^T) * (1/32) )  — fp32 acc (R9 version)
// ---------------------------------------------------------------------------
#define BM 128
#define BN 256
#define ROWB 80u
#define AS_BYTES (BM * ROWB)
#define BS_BYTES (BN * ROWB)
#define STG_BYTES (AS_BYTES + BS_BYTES)    // 30720
#define NSTAGE 3
#define GEMM_SMEM (NSTAGE * STG_BYTES)     // 92160
#define GROWB 2048
#define ITERS 32

__device__ __forceinline__ void load_stage(const char* __restrict__ Ab,
                                           const char* __restrict__ Bb,
                                           int kbyte, uint32_t stage_base, int tid)
{
#pragma unroll
    for (int j = 0; j < 2; j++) {
        int idx = tid + j * 256;
        int r = idx >> 2, c = idx & 3;
        const void* g = Ab + (size_t)r * GROWB + kbyte + c * 16;
        uint32_t sa = stage_base + (uint32_t)r * ROWB + (uint32_t)c * 16;
        asm volatile("cp.async.cg.shared.global [%0], [%1], 16;" :: "r"(sa), "l"(g));
    }
    uint32_t bs = stage_base + AS_BYTES;
#pragma unroll
    for (int j = 0; j < 4; j++) {
        int idx = tid + j * 256;
        int r = idx >> 2, c = idx & 3;
        const void* g = Bb + (size_t)r * GROWB + kbyte + c * 16;
        uint32_t sa = bs + (uint32_t)r * ROWB + (uint32_t)c * 16;
        asm volatile("cp.async.cg.shared.global [%0], [%1], 16;" :: "r"(sa), "l"(g));
    }
}

__global__ void __launch_bounds__(256, 1)
hmma_gemm()
{
    extern __shared__ char smem[];
    const uint32_t sb = smem_u32(smem);
    const int tid  = threadIdx.x;
    const int wid  = tid >> 5;
    const int lane = tid & 31;
    const int wm   = wid >> 2;
    const int wn   = wid & 3;
    const int n0   = blockIdx.x * BN;
    const int m0   = blockIdx.y * BM;
    const int which = blockIdx.z;

    const char* Ah = (const char*)g_ah[which] + (size_t)m0 * GROWB;
    const char* Bh = (const char*)g_wh[which] + (size_t)n0 * GROWB;
    __half* C = g_g16[which];

    const int quad = lane >> 3, lrow = lane & 7;
    uint32_t a_off[4], b_off[4];
#pragma unroll
    for (int mi = 0; mi < 4; mi++) {
        int row = wm * 64 + mi * 16 + (quad & 1) * 8 + lrow;
        a_off[mi] = (uint32_t)row * ROWB + (uint32_t)(quad >> 1) * 16;
    }
#pragma unroll
    for (int np = 0; np < 4; np++) {
        int row = wn * 64 + np * 16 + (quad >> 1) * 8 + lrow;
        b_off[np] = AS_BYTES + (uint32_t)row * ROWB + (uint32_t)(quad & 1) * 16;
    }

    float d[4][8][4];
#pragma unroll
    for (int mi = 0; mi < 4; mi++)
#pragma unroll
        for (int nt = 0; nt < 8; nt++)
#pragma unroll
            for (int q = 0; q < 4; q++) d[mi][nt][q] = 0.f;

    load_stage(Ah, Bh, 0, sb, tid);
    asm volatile("cp.async.commit_group;");
    load_stage(Ah, Bh, 64, sb + STG_BYTES, tid);
    asm volatile("cp.async.commit_group;");

#pragma unroll 1
    for (int it = 0; it < ITERS; it++) {
        asm volatile("cp.async.wait_group %0;" :: "n"(1) : "memory");
        __syncthreads();

        int li = it + 2;
        if (li < ITERS)
            load_stage(Ah, Bh, li * 64,
                       sb + (uint32_t)(li % NSTAGE) * STG_BYTES, tid);
        asm volatile("cp.async.commit_group;");

        const uint32_t st = sb + (uint32_t)(it % NSTAGE) * STG_BYTES;
#pragma unroll
        for (int kh = 0; kh < 2; kh++) {
            uint32_t a[4][4], b[4][4];
#pragma unroll
            for (int mi = 0; mi < 4; mi++)
                ldmx4(a[mi], st + a_off[mi] + kh * 32);
#pragma unroll
            for (int np = 0; np < 4; np++)
                ldmx4(b[np], st + b_off[np] + kh * 32);
#pragma unroll
            for (int mi = 0; mi < 4; mi++)
#pragma unroll
                for (int np = 0; np < 4; np++) {
                    mma_f16(d[mi][np * 2 + 0], a[mi], &b[np][0]);
                    mma_f16(d[mi][np * 2 + 1], a[mi], &b[np][2]);
                }
        }
    }

    const float s = 0.03125f;
    const int r_base = m0 + wm * 64 + (lane >> 2);
    const int c_base = n0 + wn * 64 + (lane & 3) * 2;
#pragma unroll
    for (int mi = 0; mi < 4; mi++) {
#pragma unroll
        for (int nt = 0; nt < 8; nt++) {
            int rr = r_base + mi * 16;
            int cc = c_base + nt * 8;
            *reinterpret_cast<__half2*>(C + (size_t)rr * FH + cc) =
                __floats2half2_rn(d[mi][nt][0] * s, d[mi][nt][1] * s);
            *reinterpret_cast<__half2*>(C + (size_t)(rr + 8) * FH + cc) =
                __floats2half2_rn(d[mi][nt][2] * s, d[mi][nt][3] * s);
        }
    }
}

// ---------------------------------------------------------------------------
// Fused LSTM epilogue: 4 batch rows per block; params loaded once into regs.
// 256 threads x 4 consecutive hidden idx per thread.
// ---------------------------------------------------------------------------
#define ROWS_PB 4

__global__ void __launch_bounds__(256)
lstm_epilogue(const float* __restrict__ c0,   const float* __restrict__ bias,
              const float* __restrict__ ln1g, const float* __restrict__ ln1b,
              const float* __restrict__ ln2g, const float* __restrict__ ln2b,
              const float* __restrict__ ln3g, const float* __restrict__ ln3b,
              float* __restrict__ out)
{
    const int b0 = blockIdx.x * ROWS_PB;
    const int t = threadIdx.x;          // 0..255
    const int warp = t >> 5;            // 0..7
    const int lane = t & 31;
    const int i0 = t * 4;               // first hidden index of this thread

    __shared__ float sm[8 * 4];

    // --- load all per-index params ONCE (reused across ROWS_PB rows) ---
    float4 G1[4], B1[4], G2[4], B2[4], BS[4];
#pragma unroll
    for (int q = 0; q < 4; q++) {
        G1[q] = *reinterpret_cast<const float4*>(ln1g + q * HH + i0);
        B1[q] = *reinterpret_cast<const float4*>(ln1b + q * HH + i0);
        G2[q] = *reinterpret_cast<const float4*>(ln2g + q * HH + i0);
        B2[q] = *reinterpret_cast<const float4*>(ln2b + q * HH + i0);
        BS[q] = *reinterpret_cast<const float4*>(bias + q * HH + i0);
    }
    float4 G3 = *reinterpret_cast<const float4*>(ln3g + i0);
    float4 B3 = *reinterpret_cast<const float4*>(ln3b + i0);
    const float* G3f = &G3.x; const float* B3f = &B3.x;

    const float inv4h = 1.f / (float)FH;
    const float invh  = 1.f / (float)HH;

#pragma unroll 1
    for (int r = 0; r < ROWS_PB; r++) {
        const int b = b0 + r;
        const __half* g1 = g_g16[0] + (size_t)b * FH;
        const __half* g2 = g_g16[1] + (size_t)b * FH;

        // barrier: previous row's readers of sm must be done before new writes
        __syncthreads();

        float v1[4][4], v2[4][4];
        float s0 = 0.f, s1 = 0.f, s2 = 0.f, s3 = 0.f;
#pragma unroll
        for (int q = 0; q < 4; q++) {
            uint2 u1 = *reinterpret_cast<const uint2*>(g1 + q * HH + i0);
            uint2 u2 = *reinterpret_cast<const uint2*>(g2 + q * HH + i0);
            float2 a01 = __half22float2(*reinterpret_cast<__half2*>(&u1.x));
            float2 a23 = __half22float2(*reinterpret_cast<__half2*>(&u1.y));
            float2 c01 = __half22float2(*reinterpret_cast<__half2*>(&u2.x));
            float2 c23 = __half22float2(*reinterpret_cast<__half2*>(&u2.y));
            v1[q][0] = a01.x; v1[q][1] = a01.y; v1[q][2] = a23.x; v1[q][3] = a23.y;
            v2[q][0] = c01.x; v2[q][1] = c01.y; v2[q][2] = c23.x; v2[q][3] = c23.y;
#pragma unroll
            for (int e = 0; e < 4; e++) {
                s0 += v1[q][e]; s1 += v1[q][e] * v1[q][e];
                s2 += v2[q][e]; s3 += v2[q][e] * v2[q][e];
            }
        }
#pragma unroll
        for (int o = 16; o > 0; o >>= 1) {
            s0 += __shfl_xor_sync(0xffffffffu, s0, o);
            s1 += __shfl_xor_sync(0xffffffffu, s1, o);
            s2 += __shfl_xor_sync(0xffffffffu, s2, o);
            s3 += __shfl_xor_sync(0xffffffffu, s3, o);
        }
        if (lane == 0) {
            sm[warp * 4 + 0] = s0; sm[warp * 4 + 1] = s1;
            sm[warp * 4 + 2] = s2; sm[warp * 4 + 3] = s3;
        }
        __syncthreads();
        float t0 = 0.f, t1 = 0.f, t2 = 0.f, t3 = 0.f;
#pragma unroll
        for (int w = 0; w < 8; w++) {
            t0 += sm[w * 4 + 0]; t1 += sm[w * 4 + 1];
            t2 += sm[w * 4 + 2]; t3 += sm[w * 4 + 3];
        }
        float mu1 = t0 * inv4h;
        float rs1 = rsqrtf(t1 * inv4h - mu1 * mu1 + EPSL);
        float mu2 = t2 * inv4h;
        float rs2 = rsqrtf(t3 * inv4h - mu2 * mu2 + EPSL);

        float gate[4][4];
#pragma unroll
        for (int q = 0; q < 4; q++) {
            const float* G1f = &G1[q].x; const float* B1f = &B1[q].x;
            const float* G2f = &G2[q].x; const float* B2f = &B2[q].x;
            const float* BSf = &BS[q].x;
#pragma unroll
            for (int e = 0; e < 4; e++)
                gate[q][e] = (v1[q][e] - mu1) * rs1 * G1f[e] + B1f[e]
                           + (v2[q][e] - mu2) * rs2 * G2f[e] + B2f[e] + BSf[e];
        }

        float4 C0 = *reinterpret_cast<const float4*>(c0 + (size_t)b * HH + i0);
        const float* C0f = &C0.x;
        float c1v[4], u0 = 0.f, u1 = 0.f;
#pragma unroll
        for (int e = 0; e < 4; e++) {
            float c1 = fsig(gate[0][e]) * C0f[e]
                     + fsig(gate[1][e]) * ftanh(gate[3][e]);
            c1v[e] = c1;
            u0 += c1; u1 += c1 * c1;
        }

        __syncthreads();   // phase-1 readers of sm done before phase-2 writes
#pragma unroll
        for (int o = 16; o > 0; o >>= 1) {
            u0 += __shfl_xor_sync(0xffffffffu, u0, o);
            u1 += __shfl_xor_sync(0xffffffffu, u1, o);
        }
        if (lane == 0) { sm[warp * 2 + 0] = u0; sm[warp * 2 + 1] = u1; }
        __syncthreads();
        float w0 = 0.f, w1 = 0.f;
#pragma unroll
        for (int w = 0; w < 8; w++) { w0 += sm[w * 2 + 0]; w1 += sm[w * 2 + 1]; }
        float mu3 = w0 * invh;
        float rs3 = rsqrtf(w1 * invh - mu3 * mu3 + EPSL);

        float4 ho, co;
        float* hof = &ho.x; float* cof = &co.x;
#pragma unroll
        for (int e = 0; e < 4; e++) {
            float hn = (c1v[e] - mu3) * rs3 * G3f[e] + B3f[e];
            hof[e] = fsig(gate[2][e]) * ftanh(hn);
            cof[e] = c1v[e];
        }
        *reinterpret_cast<float4*>(out + (size_t)b * HH + i0) = ho;
        *reinterpret_cast<float4*>(out + (size_t)BB * HH + (size_t)b * HH + i0) = co;
    }
}

// ---------------------------------------------------------------------------
// Launch
// ---------------------------------------------------------------------------
extern "C" void kernel_launch(void* const* d_in, const int* in_sizes, int n_in,
                              void* d_out, int out_size)
{
    const float* x    = (const float*)d_in[0];
    const float* h0   = (const float*)d_in[1];
    const float* c0   = (const float*)d_in[2];
    const float* Wh   = (const float*)d_in[3];
    const float* Wx   = (const float*)d_in[4];
    const float* bias = (const float*)d_in[5];
    const float* ln1g = (const float*)d_in[6];
    const float* ln1b = (const float*)d_in[7];
    const float* ln2g = (const float*)d_in[8];
    const float* ln2b = (const float*)d_in[9];
    const float* ln3g = (const float*)d_in[10];
    const float* ln3b = (const float*)d_in[11];
    float* out = (float*)d_out;

    static bool attr_set = false;
    if (!attr_set) {
        cudaFuncSetAttribute(hmma_gemm,
                             cudaFuncAttributeMaxDynamicSharedMemorySize,
                             GEMM_SMEM);
        attr_set = true;
    }

    conv_all<<<24576, 256>>>(h0, x, Wh, Wx);

    dim3 ggrid(FH / BN, BB / BM, 2);   // (16, 64, 2): both GEMMs in one launch
    hmma_gemm<<<ggrid, 256, GEMM_SMEM>>>();

    lstm_epilogue<<<BB / ROWS_PB, 256>>>(c0, bias, ln1g, ln1b, ln2g, ln2b,
                                         ln3g, ln3b, out);
}

// round 14
// speedup vs baseline: 1.1594x; 1.1594x over previous
#include <cuda_runtime.h>
#include <cuda_bf16.h>
#include <cuda_fp16.h>
#include <math.h>
#include <cstdint>

// Problem shape (fixed): B=8192, D=H=1024, 4H=4096
#define BB   8192
#define HH   1024
#define FH   4096
#define KK   1024
#define EPSL 1e-5f

// ---------------------------------------------------------------------------
// Static device scratch
// ---------------------------------------------------------------------------
__device__ __half g_g16[2][(size_t)BB * FH];
__device__ __half g_ah[2][(size_t)BB * KK];
__device__ __half g_wh[2][(size_t)FH * KK];

// ---------------------------------------------------------------------------
// helpers
// ---------------------------------------------------------------------------
__device__ __forceinline__ uint32_t smem_u32(const void* p) {
    uint32_t a;
    asm("{ .reg .u64 t; cvta.to.shared.u64 t, %1; cvt.u32.u64 %0, t; }"
        : "=r"(a) : "l"(p));
    return a;
}

__device__ __forceinline__ void ldmx4(uint32_t* r, uint32_t addr) {
    asm volatile("ldmatrix.sync.aligned.m8n8.x4.shared.b16 {%0,%1,%2,%3}, [%4];"
                 : "=r"(r[0]), "=r"(r[1]), "=r"(r[2]), "=r"(r[3]) : "r"(addr));
}

__device__ __forceinline__ void mma_f16(float* d, const uint32_t* a,
                                        const uint32_t* b) {
    asm volatile(
        "mma.sync.aligned.m16n8k16.row.col.f32.f16.f16.f32 "
        "{%0,%1,%2,%3}, {%4,%5,%6,%7}, {%8,%9}, {%0,%1,%2,%3};"
        : "+f"(d[0]), "+f"(d[1]), "+f"(d[2]), "+f"(d[3])
        : "r"(a[0]), "r"(a[1]), "r"(a[2]), "r"(a[3]), "r"(b[0]), "r"(b[1]));
}

// HW tanh (single MUFU op, sm_75+); sigmoid via tanh identity
__device__ __forceinline__ float ftanh(float x) {
    float r;
    asm("tanh.approx.f32 %0, %1;" : "=f"(r) : "f"(x));
    return r;
}
__device__ __forceinline__ float fsig(float x) {
    return fmaf(0.5f, ftanh(0.5f * x), 0.5f);
}

// ---------------------------------------------------------------------------
// Merged conversion kernel.
// blocks [0, 8192): activations, 2 float4 per thread (which = bid >> 12)
// blocks [8192, 16384): weights  (which = (bid-8192) >> 12)
// ---------------------------------------------------------------------------
__global__ void __launch_bounds__(256)
conv_all(const float* __restrict__ h0, const float* __restrict__ x,
         const float* __restrict__ Wh, const float* __restrict__ Wx)
{
    const int bid = blockIdx.x;
    if (bid < 8192) {
        const int which = bid >> 12;
        const float* in = which ? x : h0;
        size_t base = (size_t)(bid & 4095) * 512 + threadIdx.x;
#pragma unroll
        for (int j = 0; j < 2; j++) {
            size_t i = base + j * 256;                     // float4 index
            float4 v = reinterpret_cast<const float4*>(in)[i];
            __half2 p0 = __floats2half2_rn(v.x, v.y);
            __half2 p1 = __floats2half2_rn(v.z, v.w);
            __half2* dst = reinterpret_cast<__half2*>(g_ah[which]);
            dst[2 * i + 0] = p0;
            dst[2 * i + 1] = p1;
        }
    } else {
        __shared__ float ts[32][33];
        int r = bid - 8192;
        const int which = r >> 12;
        r &= 4095;
        const float* W = which ? Wx : Wh;
        int n0 = (r & 127) * 32, k0 = (r >> 7) * 32;
        int tx = threadIdx.x & 31, ty = threadIdx.x >> 5;   // ty 0..7
#pragma unroll
        for (int d = 0; d < 32; d += 8)
            ts[ty + d][tx] = W[(size_t)(k0 + ty + d) * FH + n0 + tx];
        __syncthreads();
#pragma unroll
        for (int d = 0; d < 4; d++) {
            int nl = ty + d * 8;
            float v = ts[tx][nl];
            g_wh[which][(size_t)(n0 + nl) * KK + k0 + tx] =
                __float2half_rn(32.0f * v);
        }
    }
}

// ---------------------------------------------------------------------------
// GEMM: G16[M,N] = fp16( (Ah @ (32*W)^T) * (1/32) )  — fp32 acc (R9 version)
// ---------------------------------------------------------------------------
#define BM 128
#define BN 256
#define ROWB 80u
#define AS_BYTES (BM * ROWB)
#define BS_BYTES (BN * ROWB)
#define STG_BYTES (AS_BYTES + BS_BYTES)    // 30720
#define NSTAGE 3
#define GEMM_SMEM (NSTAGE * STG_BYTES)     // 92160
#define GROWB 2048
#define ITERS 32

__device__ __forceinline__ void load_stage(const char* __restrict__ Ab,
                                           const char* __restrict__ Bb,
                                           int kbyte, uint32_t stage_base, int tid)
{
#pragma unroll
    for (int j = 0; j < 2; j++) {
        int idx = tid + j * 256;
        int r = idx >> 2, c = idx & 3;
        const void* g = Ab + (size_t)r * GROWB + kbyte + c * 16;
        uint32_t sa = stage_base + (uint32_t)r * ROWB + (uint32_t)c * 16;
        asm volatile("cp.async.cg.shared.global [%0], [%1], 16;" :: "r"(sa), "l"(g));
    }
    uint32_t bs = stage_base + AS_BYTES;
#pragma unroll
    for (int j = 0; j < 4; j++) {
        int idx = tid + j * 256;
        int r = idx >> 2, c = idx & 3;
        const void* g = Bb + (size_t)r * GROWB + kbyte + c * 16;
        uint32_t sa = bs + (uint32_t)r * ROWB + (uint32_t)c * 16;
        asm volatile("cp.async.cg.shared.global [%0], [%1], 16;" :: "r"(sa), "l"(g));
    }
}

__global__ void __launch_bounds__(256, 1)
hmma_gemm()
{
    extern __shared__ char smem[];
    const uint32_t sb = smem_u32(smem);
    const int tid  = threadIdx.x;
    const int wid  = tid >> 5;
    const int lane = tid & 31;
    const int wm   = wid >> 2;
    const int wn   = wid & 3;
    const int n0   = blockIdx.x * BN;
    const int m0   = blockIdx.y * BM;
    const int which = blockIdx.z;

    const char* Ah = (const char*)g_ah[which] + (size_t)m0 * GROWB;
    const char* Bh = (const char*)g_wh[which] + (size_t)n0 * GROWB;
    __half* C = g_g16[which];

    const int quad = lane >> 3, lrow = lane & 7;
    uint32_t a_off[4], b_off[4];
#pragma unroll
    for (int mi = 0; mi < 4; mi++) {
        int row = wm * 64 + mi * 16 + (quad & 1) * 8 + lrow;
        a_off[mi] = (uint32_t)row * ROWB + (uint32_t)(quad >> 1) * 16;
    }
#pragma unroll
    for (int np = 0; np < 4; np++) {
        int row = wn * 64 + np * 16 + (quad >> 1) * 8 + lrow;
        b_off[np] = AS_BYTES + (uint32_t)row * ROWB + (uint32_t)(quad & 1) * 16;
    }

    float d[4][8][4];
#pragma unroll
    for (int mi = 0; mi < 4; mi++)
#pragma unroll
        for (int nt = 0; nt < 8; nt++)
#pragma unroll
            for (int q = 0; q < 4; q++) d[mi][nt][q] = 0.f;

    load_stage(Ah, Bh, 0, sb, tid);
    asm volatile("cp.async.commit_group;");
    load_stage(Ah, Bh, 64, sb + STG_BYTES, tid);
    asm volatile("cp.async.commit_group;");

#pragma unroll 1
    for (int it = 0; it < ITERS; it++) {
        asm volatile("cp.async.wait_group %0;" :: "n"(1) : "memory");
        __syncthreads();

        int li = it + 2;
        if (li < ITERS)
            load_stage(Ah, Bh, li * 64,
                       sb + (uint32_t)(li % NSTAGE) * STG_BYTES, tid);
        asm volatile("cp.async.commit_group;");

        const uint32_t st = sb + (uint32_t)(it % NSTAGE) * STG_BYTES;
#pragma unroll
        for (int kh = 0; kh < 2; kh++) {
            uint32_t a[4][4], b[4][4];
#pragma unroll
            for (int mi = 0; mi < 4; mi++)
                ldmx4(a[mi], st + a_off[mi] + kh * 32);
#pragma unroll
            for (int np = 0; np < 4; np++)
                ldmx4(b[np], st + b_off[np] + kh * 32);
#pragma unroll
            for (int mi = 0; mi < 4; mi++)
#pragma unroll
                for (int np = 0; np < 4; np++) {
                    mma_f16(d[mi][np * 2 + 0], a[mi], &b[np][0]);
                    mma_f16(d[mi][np * 2 + 1], a[mi], &b[np][2]);
                }
        }
    }

    const float s = 0.03125f;
    const int r_base = m0 + wm * 64 + (lane >> 2);
    const int c_base = n0 + wn * 64 + (lane & 3) * 2;
#pragma unroll
    for (int mi = 0; mi < 4; mi++) {
#pragma unroll
        for (int nt = 0; nt < 8; nt++) {
            int rr = r_base + mi * 16;
            int cc = c_base + nt * 8;
            *reinterpret_cast<__half2*>(C + (size_t)rr * FH + cc) =
                __floats2half2_rn(d[mi][nt][0] * s, d[mi][nt][1] * s);
            *reinterpret_cast<__half2*>(C + (size_t)(rr + 8) * FH + cc) =
                __floats2half2_rn(d[mi][nt][2] * s, d[mi][nt][3] * s);
        }
    }
}

// ---------------------------------------------------------------------------
// Fused LSTM epilogue (R9 structure): 8192 blocks, 256 threads x 4 idx.
// HW-tanh transcendentals.
// ---------------------------------------------------------------------------
__global__ void __launch_bounds__(256)
lstm_epilogue(const float* __restrict__ c0,   const float* __restrict__ bias,
              const float* __restrict__ ln1g, const float* __restrict__ ln1b,
              const float* __restrict__ ln2g, const float* __restrict__ ln2b,
              const float* __restrict__ ln3g, const float* __restrict__ ln3b,
              float* __restrict__ out)
{
    const int b = blockIdx.x;
    const int t = threadIdx.x;          // 0..255
    const int warp = t >> 5;            // 0..7
    const int lane = t & 31;
    const int i0 = t * 4;               // first hidden index of this thread

    const __half* g1 = g_g16[0] + (size_t)b * FH;
    const __half* g2 = g_g16[1] + (size_t)b * FH;

    __shared__ float sm[8 * 4];

    float v1[4][4], v2[4][4];
    float s0 = 0.f, s1 = 0.f, s2 = 0.f, s3 = 0.f;
#pragma unroll
    for (int q = 0; q < 4; q++) {
        uint2 u1 = *reinterpret_cast<const uint2*>(g1 + q * HH + i0);
        uint2 u2 = *reinterpret_cast<const uint2*>(g2 + q * HH + i0);
        float2 a01 = __half22float2(*reinterpret_cast<__half2*>(&u1.x));
        float2 a23 = __half22float2(*reinterpret_cast<__half2*>(&u1.y));
        float2 c01 = __half22float2(*reinterpret_cast<__half2*>(&u2.x));
        float2 c23 = __half22float2(*reinterpret_cast<__half2*>(&u2.y));
        v1[q][0] = a01.x; v1[q][1] = a01.y; v1[q][2] = a23.x; v1[q][3] = a23.y;
        v2[q][0] = c01.x; v2[q][1] = c01.y; v2[q][2] = c23.x; v2[q][3] = c23.y;
#pragma unroll
        for (int e = 0; e < 4; e++) {
            s0 += v1[q][e]; s1 += v1[q][e] * v1[q][e];
            s2 += v2[q][e]; s3 += v2[q][e] * v2[q][e];
        }
    }
#pragma unroll
    for (int o = 16; o > 0; o >>= 1) {
        s0 += __shfl_xor_sync(0xffffffffu, s0, o);
        s1 += __shfl_xor_sync(0xffffffffu, s1, o);
        s2 += __shfl_xor_sync(0xffffffffu, s2, o);
        s3 += __shfl_xor_sync(0xffffffffu, s3, o);
    }
    if (lane == 0) {
        sm[warp * 4 + 0] = s0; sm[warp * 4 + 1] = s1;
        sm[warp * 4 + 2] = s2; sm[warp * 4 + 3] = s3;
    }
    __syncthreads();
    float t0 = 0.f, t1 = 0.f, t2 = 0.f, t3 = 0.f;
#pragma unroll
    for (int w = 0; w < 8; w++) {
        t0 += sm[w * 4 + 0]; t1 += sm[w * 4 + 1];
        t2 += sm[w * 4 + 2]; t3 += sm[w * 4 + 3];
    }
    const float inv4h = 1.f / (float)FH;
    float mu1 = t0 * inv4h;
    float rs1 = rsqrtf(t1 * inv4h - mu1 * mu1 + EPSL);
    float mu2 = t2 * inv4h;
    float rs2 = rsqrtf(t3 * inv4h - mu2 * mu2 + EPSL);

    float gate[4][4];
#pragma unroll
    for (int q = 0; q < 4; q++) {
        float4 G1 = *reinterpret_cast<const float4*>(ln1g + q * HH + i0);
        float4 B1 = *reinterpret_cast<const float4*>(ln1b + q * HH + i0);
        float4 G2 = *reinterpret_cast<const float4*>(ln2g + q * HH + i0);
        float4 B2 = *reinterpret_cast<const float4*>(ln2b + q * HH + i0);
        float4 BS = *reinterpret_cast<const float4*>(bias + q * HH + i0);
        const float* G1f = &G1.x; const float* B1f = &B1.x;
        const float* G2f = &G2.x; const float* B2f = &B2.x;
        const float* BSf = &BS.x;
#pragma unroll
        for (int e = 0; e < 4; e++)
            gate[q][e] = (v1[q][e] - mu1) * rs1 * G1f[e] + B1f[e]
                       + (v2[q][e] - mu2) * rs2 * G2f[e] + B2f[e] + BSf[e];
    }

    float4 C0 = *reinterpret_cast<const float4*>(c0 + (size_t)b * HH + i0);
    const float* C0f = &C0.x;
    float c1v[4], u0 = 0.f, u1 = 0.f;
#pragma unroll
    for (int e = 0; e < 4; e++) {
        float c1 = fsig(gate[0][e]) * C0f[e]
                 + fsig(gate[1][e]) * ftanh(gate[3][e]);
        c1v[e] = c1;
        u0 += c1; u1 += c1 * c1;
    }

    __syncthreads();
#pragma unroll
    for (int o = 16; o > 0; o >>= 1) {
        u0 += __shfl_xor_sync(0xffffffffu, u0, o);
        u1 += __shfl_xor_sync(0xffffffffu, u1, o);
    }
    if (lane == 0) { sm[warp * 2 + 0] = u0; sm[warp * 2 + 1] = u1; }
    __syncthreads();
    float w0 = 0.f, w1 = 0.f;
#pragma unroll
    for (int w = 0; w < 8; w++) { w0 += sm[w * 2 + 0]; w1 += sm[w * 2 + 1]; }
    const float invh = 1.f / (float)HH;
    float mu3 = w0 * invh;
    float rs3 = rsqrtf(w1 * invh - mu3 * mu3 + EPSL);

    float4 G3 = *reinterpret_cast<const float4*>(ln3g + i0);
    float4 B3 = *reinterpret_cast<const float4*>(ln3b + i0);
    const float* G3f = &G3.x; const float* B3f = &B3.x;
    float4 ho, co;
    float* hof = &ho.x; float* cof = &co.x;
#pragma unroll
    for (int e = 0; e < 4; e++) {
        float hn = (c1v[e] - mu3) * rs3 * G3f[e] + B3f[e];
        hof[e] = fsig(gate[2][e]) * ftanh(hn);
        cof[e] = c1v[e];
    }
    *reinterpret_cast<float4*>(out + (size_t)b * HH + i0) = ho;
    *reinterpret_cast<float4*>(out + (size_t)BB * HH + (size_t)b * HH + i0) = co;
}

// ---------------------------------------------------------------------------
// Launch
// ---------------------------------------------------------------------------
extern "C" void kernel_launch(void* const* d_in, const int* in_sizes, int n_in,
                              void* d_out, int out_size)
{
    const float* x    = (const float*)d_in[0];
    const float* h0   = (const float*)d_in[1];
    const float* c0   = (const float*)d_in[2];
    const float* Wh   = (const float*)d_in[3];
    const float* Wx   = (const float*)d_in[4];
    const float* bias = (const float*)d_in[5];
    const float* ln1g = (const float*)d_in[6];
    const float* ln1b = (const float*)d_in[7];
    const float* ln2g = (const float*)d_in[8];
    const float* ln2b = (const float*)d_in[9];
    const float* ln3g = (const float*)d_in[10];
    const float* ln3b = (const float*)d_in[11];
    float* out = (float*)d_out;

    static bool attr_set = false;
    if (!attr_set) {
        cudaFuncSetAttribute(hmma_gemm,
                             cudaFuncAttributeMaxDynamicSharedMemorySize,
                             GEMM_SMEM);
        attr_set = true;
    }

    conv_all<<<16384, 256>>>(h0, x, Wh, Wx);

    dim3 ggrid(FH / BN, BB / BM, 2);   // (16, 64, 2): both GEMMs in one launch
    hmma_gemm<<<ggrid, 256, GEMM_SMEM>>>();

    lstm_epilogue<<<BB, 256>>>(c0, bias, ln1g, ln1b, ln2g, ln2b, ln3g, ln3b, out);
}